// round 16
// baseline (speedup 1.0000x reference)
#include <cuda_runtime.h>
#include <cuda_fp16.h>
#include <cstdint>
#include <cstddef>

// ============================================================================
// WaveSubsystem, sm_103 legacy-tensor path.
//   out = tanh(c@W_mod+b_mod) * (tanh(A_diag)*0.9*w + (w@A_V)@A_U^T) + [c|z]@W_B + b_B
// R15 = R14 with G4 rebuilt: CTA 128x256, 8 warps (2x4), warp tile 64x64
// (8 MAC/B frag ratio, was 5.33), 256 CTAs = single wave, NSTAGE=2.
// Merged G1/G2/G3 kernel and pre-passes unchanged (proven).
// ============================================================================

#define BM 128
#define BN 128
#define STAGE_BYTES 32768          // merged kernel: A 16KB + B 16KB
#define NSTAGE 3
#define SMEM_TOTAL (STAGE_BYTES * NSTAGE)
#define G4_STAGE 49152             // G4: A 16KB + B 32KB per stage
#define G4_SMEM  (G4_STAGE * 2)

// ---------------- scratch (__device__ globals; allocation-free rule) --------
__device__ __half g_CZ [4096ull*3072];   // fp16 [c|z]
__device__ __half g_Wh [4096ull*2048];   // fp16 w_prev
__device__ __half g_AUh[2048ull*512];    // fp16 A_U          [N,K]
__device__ __half g_WmT[2048ull*1024];   // fp16 W_mod^T      [N,K]
__device__ __half g_WBT[2048ull*3072];   // fp16 W_B^T        [N,K]
__device__ __half g_AVT[ 512ull*2048];   // fp16 A_V^T        [N,K]
__device__ __half g_T  [4096ull*512];    // fp16 w@A_V
__device__ __half g_Y1 [4096ull*2048];   // fp16 tanh(c@W_mod+b_mod)
__device__ __half g_Y2 [4096ull*2048];   // fp16 [c|z]@W_B + b_B

// ---------------- helpers ---------------------------------------------------
__device__ __forceinline__ uint32_t smem_u32(const void* p) {
    uint32_t a;
    asm("{ .reg .u64 t; cvta.to.shared.u64 t, %1; cvt.u32.u64 %0, t; }"
        : "=r"(a) : "l"(p));
    return a;
}
__device__ __forceinline__ float tanh_ap(float x) {
    float y;
    asm("tanh.approx.f32 %0, %1;" : "=f"(y) : "f"(x));
    return y;
}
#define CP_ASYNC16(dst, src) \
    asm volatile("cp.async.cg.shared.global [%0], [%1], 16;" :: "r"(dst), "l"(src))
#define CP_COMMIT()  asm volatile("cp.async.commit_group;" ::: "memory")
#define CP_WAIT(n)   asm volatile("cp.async.wait_group %0;" :: "n"(n) : "memory")

#define LDSM_X4(r0, r1, r2, r3, addr) \
    asm volatile("ldmatrix.sync.aligned.m8n8.x4.shared.b16 {%0,%1,%2,%3}, [%4];" \
        : "=r"(r0), "=r"(r1), "=r"(r2), "=r"(r3) : "r"(addr))

__device__ __forceinline__ void mma_f16(float c[4],
                                        const uint32_t a[4],
                                        const uint32_t b[2]) {
    asm volatile(
        "mma.sync.aligned.m16n8k16.row.col.f32.f16.f16.f32 "
        "{%0,%1,%2,%3}, {%4,%5,%6,%7}, {%8,%9}, {%0,%1,%2,%3};"
        : "+f"(c[0]), "+f"(c[1]), "+f"(c[2]), "+f"(c[3])
        : "r"(a[0]), "r"(a[1]), "r"(a[2]), "r"(a[3]),
          "r"(b[0]), "r"(b[1]));
}

// ---------------- pre-pass 1: all fp32->fp16 copies (with concat restride) --
__global__ void conv_all(const float4* __restrict__ c, const float4* __restrict__ z,
                         const float4* __restrict__ w, const float4* __restrict__ au,
                         __half* __restrict__ CZ, __half* __restrict__ Wh,
                         __half* __restrict__ AUh) {
    int i = blockIdx.x * blockDim.x + threadIdx.x;
    const float4* in; __half* out; int n4, os, off;
    if (i < 1048576)      { in = c;  out = CZ;  n4 = 256; os = 3072; off = 0;    }
    else if (i < 3145728) { i -= 1048576; in = z;  out = CZ;  n4 = 512; os = 3072; off = 1024; }
    else if (i < 5242880) { i -= 3145728; in = w;  out = Wh;  n4 = 512; os = 2048; off = 0;    }
    else                  { i -= 5242880; if (i >= 262144) return;
                            in = au; out = AUh; n4 = 128; os = 512;  off = 0;    }
    int m = i / n4, k = i - m * n4;
    float4 v = in[i];
    __half2 h0 = __floats2half2_rn(v.x, v.y);
    __half2 h1 = __floats2half2_rn(v.z, v.w);
    uint2 r = make_uint2(*(uint32_t*)&h0, *(uint32_t*)&h1);
    *reinterpret_cast<uint2*>(&out[(size_t)m * os + off + 4 * k]) = r;
}

// ---------------- pre-pass 2: three transposes (fp32 [R,C] -> fp16 [C,R]) ---
__global__ void transpose3(const float* __restrict__ wb, const float* __restrict__ wm,
                           const float* __restrict__ av, __half* __restrict__ WBT,
                           __half* __restrict__ WmT, __half* __restrict__ AVT) {
    const float* in; __half* out; int R, C, gx, gy;
    if (blockIdx.z == 0)      { in = wb; out = WBT; R = 3072; C = 2048; gx = 64; gy = 96; }
    else if (blockIdx.z == 1) { in = wm; out = WmT; R = 1024; C = 2048; gx = 64; gy = 32; }
    else                      { in = av; out = AVT; R = 2048; C = 512;  gx = 16; gy = 64; }
    if ((int)blockIdx.x >= gx || (int)blockIdx.y >= gy) return;
    __shared__ float t[32][33];
    int x  = blockIdx.x * 32 + threadIdx.x;
    int y0 = blockIdx.y * 32;
    #pragma unroll
    for (int j = 0; j < 32; j += 8)
        t[threadIdx.y + j][threadIdx.x] = in[(size_t)(y0 + threadIdx.y + j) * C + x];
    __syncthreads();
    int ox  = y0 + threadIdx.x;
    int oy0 = blockIdx.x * 32;
    #pragma unroll
    for (int j = 0; j < 32; j += 8)
        out[(size_t)(oy0 + threadIdx.y + j) * R + ox] =
            __float2half_rn(t[threadIdx.x][threadIdx.y + j]);
}

// ---------------- merged GEMM G1/G2/G3: C = A @ B^T, fp16 stores ------------
struct GCfg {
    const __half* A; const __half* B;
    const float* bias; __half* C;
    int K, N, lda, epi, gx;
};
struct GCfg3 { GCfg g0, g1, g2; };

__global__ __launch_bounds__(128, 2)
void gemm_multi(GCfg3 cfgs)
{
    GCfg cf = cfgs.g0;
    if (blockIdx.z == 1) cf = cfgs.g1;
    else if (blockIdx.z == 2) cf = cfgs.g2;
    if ((int)blockIdx.x >= cf.gx) return;

    extern __shared__ __align__(128) char sm[];
    const uint32_t sb = smem_u32(sm);
    const int tid  = threadIdx.x;
    const int warp = tid >> 5, lane = tid & 31;
    const int wm = warp & 1, wn = warp >> 1;       // 2x2 warps, 64x64 tiles
    const int g  = lane >> 2, tg = lane & 3;
    const int m0 = blockIdx.y * BM, n0 = blockIdx.x * BN;
    const int K = cf.K, lda = cf.lda, N_total = cf.N;

    const int r0 = tid >> 3, jg = tid & 7;
    const __half* pA0 = cf.A + (size_t)(m0 + r0) * lda + jg * 8;
    const __half* pB0 = cf.B + (size_t)(n0 + r0) * K + jg * 8;
    const size_t aStep = (size_t)16 * lda;
    const size_t bStep = (size_t)16 * K;
    const uint32_t dA0 = r0 * 128 + ((jg ^ (r0 & 7)) << 4);
    const uint32_t dB0 = 16384u + dA0;

    const int mA = lane >> 3, iA = lane & 7;
    uint32_t aBase[4], aXor[4];
    #pragma unroll
    for (int mi = 0; mi < 4; mi++) {
        int row = wm * 64 + mi * 16 + (mA & 1) * 8 + iA;
        aBase[mi] = (uint32_t)row * 128;
        aXor[mi]  = (uint32_t)(row & 7);
    }
    const uint32_t aHi = (uint32_t)(mA >> 1);
    uint32_t bBase[4], bXor[4];
    #pragma unroll
    for (int p = 0; p < 4; p++) {
        int row = wn * 64 + p * 16 + ((mA >> 1) << 3) + iA;
        bBase[p] = 16384u + (uint32_t)row * 128;
        bXor[p]  = (uint32_t)(row & 7);
    }
    const uint32_t bHi = (uint32_t)(mA & 1);

    float acc[4][8][4];
    #pragma unroll
    for (int mi = 0; mi < 4; mi++)
        #pragma unroll
        for (int ni = 0; ni < 8; ni++)
            #pragma unroll
            for (int q = 0; q < 4; q++) acc[mi][ni][q] = 0.f;

    const int KT = K >> 6;                     // BK = 64
    auto produce = [&](int kt) {
        uint32_t base = sb + (uint32_t)(kt % NSTAGE) * STAGE_BYTES;
        int ko = kt << 6;
        #pragma unroll
        for (int i = 0; i < 8; i++) CP_ASYNC16(base + dA0 + i * 2048, pA0 + i * aStep + ko);
        #pragma unroll
        for (int i = 0; i < 8; i++) CP_ASYNC16(base + dB0 + i * 2048, pB0 + i * bStep + ko);
        CP_COMMIT();
    };

    produce(0);
    produce(1);
    #pragma unroll 1
    for (int kt = 0; kt < KT; kt++) {
        if (kt == KT - 1) { CP_WAIT(0); } else { CP_WAIT(1); }
        __syncthreads();
        if (kt + 2 < KT) produce(kt + 2);

        const uint32_t sBase = sb + (uint32_t)(kt % NSTAGE) * STAGE_BYTES;

        #pragma unroll
        for (int ks = 0; ks < 4; ks++) {
            uint32_t bf[8][2];
            #pragma unroll
            for (int p = 0; p < 4; p++) {
                uint32_t addr = sBase + bBase[p] + (((2u*ks + bHi) ^ bXor[p]) << 4);
                LDSM_X4(bf[2*p][0], bf[2*p][1], bf[2*p+1][0], bf[2*p+1][1], addr);
            }
            #pragma unroll
            for (int mi = 0; mi < 4; mi++) {
                uint32_t af[4];
                uint32_t addr = sBase + aBase[mi] + (((2u*ks + aHi) ^ aXor[mi]) << 4);
                LDSM_X4(af[0], af[1], af[2], af[3], addr);
                #pragma unroll
                for (int ni = 0; ni < 8; ni++)
                    mma_f16(acc[mi][ni], af, bf[ni]);
            }
        }
    }

    const int epi = cf.epi;
    #pragma unroll
    for (int mi = 0; mi < 4; mi++) {
        #pragma unroll
        for (int rr = 0; rr < 2; rr++) {
            int row = m0 + wm * 64 + mi * 16 + g + rr * 8;
            #pragma unroll
            for (int ni = 0; ni < 8; ni++) {
                int col = n0 + wn * 64 + ni * 8 + tg * 2;
                size_t idx = (size_t)row * N_total + col;
                float v0 = acc[mi][ni][rr * 2 + 0];
                float v1 = acc[mi][ni][rr * 2 + 1];
                if (epi == 3) {
                    v0 = tanh_ap(v0 + cf.bias[col]); v1 = tanh_ap(v1 + cf.bias[col + 1]);
                } else if (epi == 4) {
                    v0 += cf.bias[col]; v1 += cf.bias[col + 1];
                }
                __half2 h = __floats2half2_rn(v0, v1);
                *reinterpret_cast<__half2*>(&cf.C[idx]) = h;
            }
        }
    }
}

// ---------------- G4: out = Y1 * (ad*w + T@AU^T) + Y2 -----------------------
// CTA 128x256, 8 warps (2x4), warp tile 64x64, K=512, NSTAGE=2 double buffer.
__global__ __launch_bounds__(256, 2)
void gemm_g4(const __half* __restrict__ A,   // T   [4096,512]
             const __half* __restrict__ B,   // AUh [2048,512]
             const __half* __restrict__ Y1h,
             const __half* __restrict__ Y2h,
             const __half* __restrict__ Wh,
             const float* __restrict__ Ad,
             float* __restrict__ out)
{
    extern __shared__ __align__(128) char sm[];
    const uint32_t sb = smem_u32(sm);
    const int tid  = threadIdx.x;
    const int warp = tid >> 5, lane = tid & 31;
    const int wm = warp & 1, wn = warp >> 1;       // 2x4 warps, 64x64 tiles
    const int g  = lane >> 2, tg = lane & 3;
    const int m0 = blockIdx.y * 128, n0 = blockIdx.x * 256;
    const int K = 512, N_total = 2048;

    // producer: A 128 rows x 8 granules (4/thread), B 256 rows x 8 (8/thread)
    const int r0 = tid >> 3, jg = tid & 7;         // r0: 0..31
    const __half* pA0 = A + (size_t)(m0 + r0) * K + jg * 8;
    const __half* pB0 = B + (size_t)(n0 + r0) * K + jg * 8;
    const size_t rStep = (size_t)32 * K;
    const uint32_t dA0 = r0 * 128 + ((jg ^ (r0 & 7)) << 4);
    const uint32_t dB0 = 16384u + dA0;

    const int mA = lane >> 3, iA = lane & 7;
    uint32_t aBase[4], aXor[4];
    #pragma unroll
    for (int mi = 0; mi < 4; mi++) {
        int row = wm * 64 + mi * 16 + (mA & 1) * 8 + iA;
        aBase[mi] = (uint32_t)row * 128;
        aXor[mi]  = (uint32_t)(row & 7);
    }
    const uint32_t aHi = (uint32_t)(mA >> 1);
    uint32_t bBase[4], bXor[4];
    #pragma unroll
    for (int p = 0; p < 4; p++) {
        int row = wn * 64 + p * 16 + ((mA >> 1) << 3) + iA;
        bBase[p] = 16384u + (uint32_t)row * 128;
        bXor[p]  = (uint32_t)(row & 7);
    }
    const uint32_t bHi = (uint32_t)(mA & 1);

    float acc[4][8][4];
    #pragma unroll
    for (int mi = 0; mi < 4; mi++)
        #pragma unroll
        for (int ni = 0; ni < 8; ni++)
            #pragma unroll
            for (int q = 0; q < 4; q++) acc[mi][ni][q] = 0.f;

    const int KT = K >> 6;                     // 8
    auto produce = [&](int kt) {
        uint32_t base = sb + (uint32_t)(kt & 1) * G4_STAGE;
        int ko = kt << 6;
        #pragma unroll
        for (int i = 0; i < 4; i++) CP_ASYNC16(base + dA0 + i * 4096, pA0 + i * rStep + ko);
        #pragma unroll
        for (int i = 0; i < 8; i++) CP_ASYNC16(base + dB0 + i * 4096, pB0 + i * rStep + ko);
        CP_COMMIT();
    };

    produce(0);
    produce(1);
    #pragma unroll 1
    for (int kt = 0; kt < KT; kt++) {
        if (kt == KT - 1) { CP_WAIT(0); } else { CP_WAIT(1); }
        __syncthreads();                       // stage kt ready

        const uint32_t sBase = sb + (uint32_t)(kt & 1) * G4_STAGE;

        #pragma unroll
        for (int ks = 0; ks < 4; ks++) {
            uint32_t bf[8][2];
            #pragma unroll
            for (int p = 0; p < 4; p++) {
                uint32_t addr = sBase + bBase[p] + (((2u*ks + bHi) ^ bXor[p]) << 4);
                LDSM_X4(bf[2*p][0], bf[2*p][1], bf[2*p+1][0], bf[2*p+1][1], addr);
            }
            #pragma unroll
            for (int mi = 0; mi < 4; mi++) {
                uint32_t af[4];
                uint32_t addr = sBase + aBase[mi] + (((2u*ks + aHi) ^ aXor[mi]) << 4);
                LDSM_X4(af[0], af[1], af[2], af[3], addr);
                #pragma unroll
                for (int ni = 0; ni < 8; ni++)
                    mma_f16(acc[mi][ni], af, bf[ni]);
            }
        }
        if (kt + 2 < KT) {                     // double buffer: drain reads
            __syncthreads();                   // before overwriting stage kt&1
            produce(kt + 2);
        }
    }

    // ---- fused epilogue ----
    float adv[8][2];
    #pragma unroll
    for (int ni = 0; ni < 8; ni++) {
        int col = n0 + wn * 64 + ni * 8 + tg * 2;
        adv[ni][0] = tanh_ap(Ad[col])     * 0.9f;
        adv[ni][1] = tanh_ap(Ad[col + 1]) * 0.9f;
    }
    #pragma unroll
    for (int mi = 0; mi < 4; mi++) {
        #pragma unroll
        for (int rr = 0; rr < 2; rr++) {
            int row = m0 + wm * 64 + mi * 16 + g + rr * 8;
            size_t rbase = (size_t)row * N_total;
            float2 y1v[8], y2v[8], wv[8];
            #pragma unroll
            for (int ni = 0; ni < 8; ni++) {
                int col = n0 + wn * 64 + ni * 8 + tg * 2;
                y1v[ni] = __half22float2(*reinterpret_cast<const __half2*>(&Y1h[rbase + col]));
                y2v[ni] = __half22float2(*reinterpret_cast<const __half2*>(&Y2h[rbase + col]));
                wv[ni]  = __half22float2(*reinterpret_cast<const __half2*>(&Wh[rbase + col]));
            }
            #pragma unroll
            for (int ni = 0; ni < 8; ni++) {
                int col = n0 + wn * 64 + ni * 8 + tg * 2;
                float v0 = acc[mi][ni][rr * 2 + 0];
                float v1 = acc[mi][ni][rr * 2 + 1];
                float o0 = y1v[ni].x * (adv[ni][0] * wv[ni].x + v0) + y2v[ni].x;
                float o1 = y1v[ni].y * (adv[ni][1] * wv[ni].y + v1) + y2v[ni].y;
                *reinterpret_cast<float2*>(&out[rbase + col]) = make_float2(o0, o1);
            }
        }
    }
}

// ---------------- host ------------------------------------------------------
extern "C" void kernel_launch(void* const* d_in, const int* in_sizes, int n_in,
                              void* d_out, int out_size)
{
    const float* w_prev = (const float*)d_in[0];   // [4096,2048]
    const float* z_t    = (const float*)d_in[1];   // [4096,2048]
    const float* c_t    = (const float*)d_in[2];   // [4096,1024]
    const float* A_diag = (const float*)d_in[3];   // [2048]
    const float* A_U    = (const float*)d_in[4];   // [2048,512]
    const float* A_V    = (const float*)d_in[5];   // [2048,512]
    const float* W_mod  = (const float*)d_in[6];   // [1024,2048]
    const float* b_mod  = (const float*)d_in[7];
    const float* W_B    = (const float*)d_in[8];   // [3072,2048]
    const float* b_B    = (const float*)d_in[9];
    float* out = (float*)d_out;                    // [4096,2048]
    (void)in_sizes; (void)n_in; (void)out_size;

    __half *CZ, *Wh, *AUh, *WmT, *WBT, *AVT, *T, *Y1, *Y2;
    cudaGetSymbolAddress((void**)&CZ,  g_CZ);
    cudaGetSymbolAddress((void**)&Wh,  g_Wh);
    cudaGetSymbolAddress((void**)&AUh, g_AUh);
    cudaGetSymbolAddress((void**)&WmT, g_WmT);
    cudaGetSymbolAddress((void**)&WBT, g_WBT);
    cudaGetSymbolAddress((void**)&AVT, g_AVT);
    cudaGetSymbolAddress((void**)&T,   g_T);
    cudaGetSymbolAddress((void**)&Y1,  g_Y1);
    cudaGetSymbolAddress((void**)&Y2,  g_Y2);

    cudaFuncSetAttribute(gemm_multi, cudaFuncAttributeMaxDynamicSharedMemorySize, SMEM_TOTAL);
    cudaFuncSetAttribute(gemm_g4,    cudaFuncAttributeMaxDynamicSharedMemorySize, G4_SMEM);

    // pre-pass 1: all fp32->fp16 copies (c|z concat, w_prev, A_U)
    conv_all<<<21504, 256>>>((const float4*)c_t, (const float4*)z_t,
                             (const float4*)w_prev, (const float4*)A_U,
                             CZ, Wh, AUh);
    // pre-pass 2: three weight transposes
    transpose3<<<dim3(64, 96, 3), dim3(32, 8)>>>(W_B, W_mod, A_V, WBT, WmT, AVT);

    // merged G2 (z=0, longest K first) + G1 (z=1) + G3 (z=2)
    GCfg3 cf;
    cf.g0 = { CZ, WBT, b_B,   Y2, 3072, 2048, 3072, 4, 16 };  // G2 -> fp16
    cf.g1 = { CZ, WmT, b_mod, Y1, 1024, 2048, 3072, 3, 16 };  // G1 tanh -> fp16
    cf.g2 = { Wh, AVT, nullptr, T, 2048, 512, 2048, 1, 4 };   // G3 -> fp16
    gemm_multi<<<dim3(16, 32, 3), 128, SMEM_TOTAL>>>(cf);

    // G4 fused finale: CTA 128x256, single wave (8x32 = 256 CTAs)
    gemm_g4<<<dim3(8, 32), 256, G4_SMEM>>>(T, AUh, Y1, Y2, Wh, A_diag, out);
}

// round 17
// speedup vs baseline: 1.2099x; 1.2099x over previous
#include <cuda_runtime.h>
#include <cuda_fp16.h>
#include <cstdint>
#include <cstddef>

// ============================================================================
// WaveSubsystem, sm_103 legacy-tensor path.
//   out = tanh(c@W_mod+b_mod) * (tanh(A_diag)*0.9*w + (w@A_V)@A_U^T) + [c|z]@W_B + b_B
// R16: G4 rebuilt in the PROVEN merged-kernel geometry (128 threads, 4 warps,
// 64x64 warp tile, launch_bounds(128,2) -> 255-reg budget, no spills) with the
// fused fp16-stream epilogue. R15's 256-thread 64x64 variant spilled (cap 128
// regs) -> L2 48.6% local traffic, 101 us. Everything else = R14 (proven).
// ============================================================================

#define BM 128
#define BN 128
#define STAGE_BYTES 32768          // A 16KB + B 16KB (fp16, BK=64)
#define NSTAGE 3
#define SMEM_TOTAL (STAGE_BYTES * NSTAGE)

// ---------------- scratch (__device__ globals; allocation-free rule) --------
__device__ __half g_CZ [4096ull*3072];   // fp16 [c|z]
__device__ __half g_Wh [4096ull*2048];   // fp16 w_prev
__device__ __half g_AUh[2048ull*512];    // fp16 A_U          [N,K]
__device__ __half g_WmT[2048ull*1024];   // fp16 W_mod^T      [N,K]
__device__ __half g_WBT[2048ull*3072];   // fp16 W_B^T        [N,K]
__device__ __half g_AVT[ 512ull*2048];   // fp16 A_V^T        [N,K]
__device__ __half g_T  [4096ull*512];    // fp16 w@A_V
__device__ __half g_Y1 [4096ull*2048];   // fp16 tanh(c@W_mod+b_mod)
__device__ __half g_Y2 [4096ull*2048];   // fp16 [c|z]@W_B + b_B

// ---------------- helpers ---------------------------------------------------
__device__ __forceinline__ uint32_t smem_u32(const void* p) {
    uint32_t a;
    asm("{ .reg .u64 t; cvta.to.shared.u64 t, %1; cvt.u32.u64 %0, t; }"
        : "=r"(a) : "l"(p));
    return a;
}
__device__ __forceinline__ float tanh_ap(float x) {
    float y;
    asm("tanh.approx.f32 %0, %1;" : "=f"(y) : "f"(x));
    return y;
}
#define CP_ASYNC16(dst, src) \
    asm volatile("cp.async.cg.shared.global [%0], [%1], 16;" :: "r"(dst), "l"(src))
#define CP_COMMIT()  asm volatile("cp.async.commit_group;" ::: "memory")
#define CP_WAIT(n)   asm volatile("cp.async.wait_group %0;" :: "n"(n) : "memory")

#define LDSM_X4(r0, r1, r2, r3, addr) \
    asm volatile("ldmatrix.sync.aligned.m8n8.x4.shared.b16 {%0,%1,%2,%3}, [%4];" \
        : "=r"(r0), "=r"(r1), "=r"(r2), "=r"(r3) : "r"(addr))

__device__ __forceinline__ void mma_f16(float c[4],
                                        const uint32_t a[4],
                                        const uint32_t b[2]) {
    asm volatile(
        "mma.sync.aligned.m16n8k16.row.col.f32.f16.f16.f32 "
        "{%0,%1,%2,%3}, {%4,%5,%6,%7}, {%8,%9}, {%0,%1,%2,%3};"
        : "+f"(c[0]), "+f"(c[1]), "+f"(c[2]), "+f"(c[3])
        : "r"(a[0]), "r"(a[1]), "r"(a[2]), "r"(a[3]),
          "r"(b[0]), "r"(b[1]));
}

// ---------------- pre-pass 1: all fp32->fp16 copies (with concat restride) --
__global__ void conv_all(const float4* __restrict__ c, const float4* __restrict__ z,
                         const float4* __restrict__ w, const float4* __restrict__ au,
                         __half* __restrict__ CZ, __half* __restrict__ Wh,
                         __half* __restrict__ AUh) {
    int i = blockIdx.x * blockDim.x + threadIdx.x;
    const float4* in; __half* out; int n4, os, off;
    if (i < 1048576)      { in = c;  out = CZ;  n4 = 256; os = 3072; off = 0;    }
    else if (i < 3145728) { i -= 1048576; in = z;  out = CZ;  n4 = 512; os = 3072; off = 1024; }
    else if (i < 5242880) { i -= 3145728; in = w;  out = Wh;  n4 = 512; os = 2048; off = 0;    }
    else                  { i -= 5242880; if (i >= 262144) return;
                            in = au; out = AUh; n4 = 128; os = 512;  off = 0;    }
    int m = i / n4, k = i - m * n4;
    float4 v = in[i];
    __half2 h0 = __floats2half2_rn(v.x, v.y);
    __half2 h1 = __floats2half2_rn(v.z, v.w);
    uint2 r = make_uint2(*(uint32_t*)&h0, *(uint32_t*)&h1);
    *reinterpret_cast<uint2*>(&out[(size_t)m * os + off + 4 * k]) = r;
}

// ---------------- pre-pass 2: three transposes (fp32 [R,C] -> fp16 [C,R]) ---
__global__ void transpose3(const float* __restrict__ wb, const float* __restrict__ wm,
                           const float* __restrict__ av, __half* __restrict__ WBT,
                           __half* __restrict__ WmT, __half* __restrict__ AVT) {
    const float* in; __half* out; int R, C, gx, gy;
    if (blockIdx.z == 0)      { in = wb; out = WBT; R = 3072; C = 2048; gx = 64; gy = 96; }
    else if (blockIdx.z == 1) { in = wm; out = WmT; R = 1024; C = 2048; gx = 64; gy = 32; }
    else                      { in = av; out = AVT; R = 2048; C = 512;  gx = 16; gy = 64; }
    if ((int)blockIdx.x >= gx || (int)blockIdx.y >= gy) return;
    __shared__ float t[32][33];
    int x  = blockIdx.x * 32 + threadIdx.x;
    int y0 = blockIdx.y * 32;
    #pragma unroll
    for (int j = 0; j < 32; j += 8)
        t[threadIdx.y + j][threadIdx.x] = in[(size_t)(y0 + threadIdx.y + j) * C + x];
    __syncthreads();
    int ox  = y0 + threadIdx.x;
    int oy0 = blockIdx.x * 32;
    #pragma unroll
    for (int j = 0; j < 32; j += 8)
        out[(size_t)(oy0 + threadIdx.y + j) * R + ox] =
            __float2half_rn(t[threadIdx.x][threadIdx.y + j]);
}

// ---------------- merged GEMM G1/G2/G3: C = A @ B^T, fp16 stores ------------
struct GCfg {
    const __half* A; const __half* B;
    const float* bias; __half* C;
    int K, N, lda, epi, gx;
};
struct GCfg3 { GCfg g0, g1, g2; };

__global__ __launch_bounds__(128, 2)
void gemm_multi(GCfg3 cfgs)
{
    GCfg cf = cfgs.g0;
    if (blockIdx.z == 1) cf = cfgs.g1;
    else if (blockIdx.z == 2) cf = cfgs.g2;
    if ((int)blockIdx.x >= cf.gx) return;

    extern __shared__ __align__(128) char sm[];
    const uint32_t sb = smem_u32(sm);
    const int tid  = threadIdx.x;
    const int warp = tid >> 5, lane = tid & 31;
    const int wm = warp & 1, wn = warp >> 1;       // 2x2 warps, 64x64 tiles
    const int g  = lane >> 2, tg = lane & 3;
    const int m0 = blockIdx.y * BM, n0 = blockIdx.x * BN;
    const int K = cf.K, lda = cf.lda, N_total = cf.N;

    const int r0 = tid >> 3, jg = tid & 7;
    const __half* pA0 = cf.A + (size_t)(m0 + r0) * lda + jg * 8;
    const __half* pB0 = cf.B + (size_t)(n0 + r0) * K + jg * 8;
    const size_t aStep = (size_t)16 * lda;
    const size_t bStep = (size_t)16 * K;
    const uint32_t dA0 = r0 * 128 + ((jg ^ (r0 & 7)) << 4);
    const uint32_t dB0 = 16384u + dA0;

    const int mA = lane >> 3, iA = lane & 7;
    uint32_t aBase[4], aXor[4];
    #pragma unroll
    for (int mi = 0; mi < 4; mi++) {
        int row = wm * 64 + mi * 16 + (mA & 1) * 8 + iA;
        aBase[mi] = (uint32_t)row * 128;
        aXor[mi]  = (uint32_t)(row & 7);
    }
    const uint32_t aHi = (uint32_t)(mA >> 1);
    uint32_t bBase[4], bXor[4];
    #pragma unroll
    for (int p = 0; p < 4; p++) {
        int row = wn * 64 + p * 16 + ((mA >> 1) << 3) + iA;
        bBase[p] = 16384u + (uint32_t)row * 128;
        bXor[p]  = (uint32_t)(row & 7);
    }
    const uint32_t bHi = (uint32_t)(mA & 1);

    float acc[4][8][4];
    #pragma unroll
    for (int mi = 0; mi < 4; mi++)
        #pragma unroll
        for (int ni = 0; ni < 8; ni++)
            #pragma unroll
            for (int q = 0; q < 4; q++) acc[mi][ni][q] = 0.f;

    const int KT = K >> 6;                     // BK = 64
    auto produce = [&](int kt) {
        uint32_t base = sb + (uint32_t)(kt % NSTAGE) * STAGE_BYTES;
        int ko = kt << 6;
        #pragma unroll
        for (int i = 0; i < 8; i++) CP_ASYNC16(base + dA0 + i * 2048, pA0 + i * aStep + ko);
        #pragma unroll
        for (int i = 0; i < 8; i++) CP_ASYNC16(base + dB0 + i * 2048, pB0 + i * bStep + ko);
        CP_COMMIT();
    };

    produce(0);
    produce(1);
    #pragma unroll 1
    for (int kt = 0; kt < KT; kt++) {
        if (kt == KT - 1) { CP_WAIT(0); } else { CP_WAIT(1); }
        __syncthreads();
        if (kt + 2 < KT) produce(kt + 2);

        const uint32_t sBase = sb + (uint32_t)(kt % NSTAGE) * STAGE_BYTES;

        #pragma unroll
        for (int ks = 0; ks < 4; ks++) {
            uint32_t bf[8][2];
            #pragma unroll
            for (int p = 0; p < 4; p++) {
                uint32_t addr = sBase + bBase[p] + (((2u*ks + bHi) ^ bXor[p]) << 4);
                LDSM_X4(bf[2*p][0], bf[2*p][1], bf[2*p+1][0], bf[2*p+1][1], addr);
            }
            #pragma unroll
            for (int mi = 0; mi < 4; mi++) {
                uint32_t af[4];
                uint32_t addr = sBase + aBase[mi] + (((2u*ks + aHi) ^ aXor[mi]) << 4);
                LDSM_X4(af[0], af[1], af[2], af[3], addr);
                #pragma unroll
                for (int ni = 0; ni < 8; ni++)
                    mma_f16(acc[mi][ni], af, bf[ni]);
            }
        }
    }

    const int epi = cf.epi;
    #pragma unroll
    for (int mi = 0; mi < 4; mi++) {
        #pragma unroll
        for (int rr = 0; rr < 2; rr++) {
            int row = m0 + wm * 64 + mi * 16 + g + rr * 8;
            #pragma unroll
            for (int ni = 0; ni < 8; ni++) {
                int col = n0 + wn * 64 + ni * 8 + tg * 2;
                size_t idx = (size_t)row * N_total + col;
                float v0 = acc[mi][ni][rr * 2 + 0];
                float v1 = acc[mi][ni][rr * 2 + 1];
                if (epi == 3) {
                    v0 = tanh_ap(v0 + cf.bias[col]); v1 = tanh_ap(v1 + cf.bias[col + 1]);
                } else if (epi == 4) {
                    v0 += cf.bias[col]; v1 += cf.bias[col + 1];
                }
                __half2 h = __floats2half2_rn(v0, v1);
                *reinterpret_cast<__half2*>(&cf.C[idx]) = h;
            }
        }
    }
}

// ---------------- G4: out = Y1 * (ad*w + T@AU^T) + Y2 -----------------------
// Proven merged-kernel geometry: 128 threads, 4 warps (2x2), 64x64 warp tile,
// CTA 128x128, NSTAGE=3 ring, launch_bounds(128,2) -> 255-reg budget.
__global__ __launch_bounds__(128, 2)
void gemm_g4(const __half* __restrict__ A,   // T   [4096,512]
             const __half* __restrict__ B,   // AUh [2048,512]
             const __half* __restrict__ Y1h,
             const __half* __restrict__ Y2h,
             const __half* __restrict__ Wh,
             const float* __restrict__ Ad,
             float* __restrict__ out)
{
    extern __shared__ __align__(128) char sm[];
    const uint32_t sb = smem_u32(sm);
    const int tid  = threadIdx.x;
    const int warp = tid >> 5, lane = tid & 31;
    const int wm = warp & 1, wn = warp >> 1;       // 2x2 warps, 64x64 tiles
    const int g  = lane >> 2, tg = lane & 3;
    const int m0 = blockIdx.y * BM, n0 = blockIdx.x * BN;
    const int K = 512, N_total = 2048;

    const int r0 = tid >> 3, jg = tid & 7;
    const __half* pA0 = A + (size_t)(m0 + r0) * K + jg * 8;
    const __half* pB0 = B + (size_t)(n0 + r0) * K + jg * 8;
    const size_t step = (size_t)16 * K;
    const uint32_t dA0 = r0 * 128 + ((jg ^ (r0 & 7)) << 4);
    const uint32_t dB0 = 16384u + dA0;

    const int mA = lane >> 3, iA = lane & 7;
    uint32_t aBase[4], aXor[4];
    #pragma unroll
    for (int mi = 0; mi < 4; mi++) {
        int row = wm * 64 + mi * 16 + (mA & 1) * 8 + iA;
        aBase[mi] = (uint32_t)row * 128;
        aXor[mi]  = (uint32_t)(row & 7);
    }
    const uint32_t aHi = (uint32_t)(mA >> 1);
    uint32_t bBase[4], bXor[4];
    #pragma unroll
    for (int p = 0; p < 4; p++) {
        int row = wn * 64 + p * 16 + ((mA >> 1) << 3) + iA;
        bBase[p] = 16384u + (uint32_t)row * 128;
        bXor[p]  = (uint32_t)(row & 7);
    }
    const uint32_t bHi = (uint32_t)(mA & 1);

    float acc[4][8][4];
    #pragma unroll
    for (int mi = 0; mi < 4; mi++)
        #pragma unroll
        for (int ni = 0; ni < 8; ni++)
            #pragma unroll
            for (int q = 0; q < 4; q++) acc[mi][ni][q] = 0.f;

    const int KT = K >> 6;                     // 8
    auto produce = [&](int kt) {
        uint32_t base = sb + (uint32_t)(kt % NSTAGE) * STAGE_BYTES;
        int ko = kt << 6;
        #pragma unroll
        for (int i = 0; i < 8; i++) CP_ASYNC16(base + dA0 + i * 2048, pA0 + i * step + ko);
        #pragma unroll
        for (int i = 0; i < 8; i++) CP_ASYNC16(base + dB0 + i * 2048, pB0 + i * step + ko);
        CP_COMMIT();
    };

    produce(0);
    produce(1);
    #pragma unroll 1
    for (int kt = 0; kt < KT; kt++) {
        if (kt == KT - 1) { CP_WAIT(0); } else { CP_WAIT(1); }
        __syncthreads();
        if (kt + 2 < KT) produce(kt + 2);

        const uint32_t sBase = sb + (uint32_t)(kt % NSTAGE) * STAGE_BYTES;

        #pragma unroll
        for (int ks = 0; ks < 4; ks++) {
            uint32_t bf[8][2];
            #pragma unroll
            for (int p = 0; p < 4; p++) {
                uint32_t addr = sBase + bBase[p] + (((2u*ks + bHi) ^ bXor[p]) << 4);
                LDSM_X4(bf[2*p][0], bf[2*p][1], bf[2*p+1][0], bf[2*p+1][1], addr);
            }
            #pragma unroll
            for (int mi = 0; mi < 4; mi++) {
                uint32_t af[4];
                uint32_t addr = sBase + aBase[mi] + (((2u*ks + aHi) ^ aXor[mi]) << 4);
                LDSM_X4(af[0], af[1], af[2], af[3], addr);
                #pragma unroll
                for (int ni = 0; ni < 8; ni++)
                    mma_f16(acc[mi][ni], af, bf[ni]);
            }
        }
    }

    // ---- fused epilogue: fp16 streams, tanh.approx, batched loads ----
    float adv[8][2];
    #pragma unroll
    for (int ni = 0; ni < 8; ni++) {
        int col = n0 + wn * 64 + ni * 8 + tg * 2;
        adv[ni][0] = tanh_ap(Ad[col])     * 0.9f;
        adv[ni][1] = tanh_ap(Ad[col + 1]) * 0.9f;
    }
    #pragma unroll
    for (int mi = 0; mi < 4; mi++) {
        #pragma unroll
        for (int rr = 0; rr < 2; rr++) {
            int row = m0 + wm * 64 + mi * 16 + g + rr * 8;
            size_t rbase = (size_t)row * N_total;
            float2 y1v[8], y2v[8], wv[8];
            #pragma unroll
            for (int ni = 0; ni < 8; ni++) {
                int col = n0 + wn * 64 + ni * 8 + tg * 2;
                y1v[ni] = __half22float2(*reinterpret_cast<const __half2*>(&Y1h[rbase + col]));
                y2v[ni] = __half22float2(*reinterpret_cast<const __half2*>(&Y2h[rbase + col]));
                wv[ni]  = __half22float2(*reinterpret_cast<const __half2*>(&Wh[rbase + col]));
            }
            #pragma unroll
            for (int ni = 0; ni < 8; ni++) {
                int col = n0 + wn * 64 + ni * 8 + tg * 2;
                float v0 = acc[mi][ni][rr * 2 + 0];
                float v1 = acc[mi][ni][rr * 2 + 1];
                float o0 = y1v[ni].x * (adv[ni][0] * wv[ni].x + v0) + y2v[ni].x;
                float o1 = y1v[ni].y * (adv[ni][1] * wv[ni].y + v1) + y2v[ni].y;
                *reinterpret_cast<float2*>(&out[rbase + col]) = make_float2(o0, o1);
            }
        }
    }
}

// ---------------- host ------------------------------------------------------
extern "C" void kernel_launch(void* const* d_in, const int* in_sizes, int n_in,
                              void* d_out, int out_size)
{
    const float* w_prev = (const float*)d_in[0];   // [4096,2048]
    const float* z_t    = (const float*)d_in[1];   // [4096,2048]
    const float* c_t    = (const float*)d_in[2];   // [4096,1024]
    const float* A_diag = (const float*)d_in[3];   // [2048]
    const float* A_U    = (const float*)d_in[4];   // [2048,512]
    const float* A_V    = (const float*)d_in[5];   // [2048,512]
    const float* W_mod  = (const float*)d_in[6];   // [1024,2048]
    const float* b_mod  = (const float*)d_in[7];
    const float* W_B    = (const float*)d_in[8];   // [3072,2048]
    const float* b_B    = (const float*)d_in[9];
    float* out = (float*)d_out;                    // [4096,2048]
    (void)in_sizes; (void)n_in; (void)out_size;

    __half *CZ, *Wh, *AUh, *WmT, *WBT, *AVT, *T, *Y1, *Y2;
    cudaGetSymbolAddress((void**)&CZ,  g_CZ);
    cudaGetSymbolAddress((void**)&Wh,  g_Wh);
    cudaGetSymbolAddress((void**)&AUh, g_AUh);
    cudaGetSymbolAddress((void**)&WmT, g_WmT);
    cudaGetSymbolAddress((void**)&WBT, g_WBT);
    cudaGetSymbolAddress((void**)&AVT, g_AVT);
    cudaGetSymbolAddress((void**)&T,   g_T);
    cudaGetSymbolAddress((void**)&Y1,  g_Y1);
    cudaGetSymbolAddress((void**)&Y2,  g_Y2);

    cudaFuncSetAttribute(gemm_multi, cudaFuncAttributeMaxDynamicSharedMemorySize, SMEM_TOTAL);
    cudaFuncSetAttribute(gemm_g4,    cudaFuncAttributeMaxDynamicSharedMemorySize, SMEM_TOTAL);

    // pre-pass 1: all fp32->fp16 copies (c|z concat, w_prev, A_U)
    conv_all<<<21504, 256>>>((const float4*)c_t, (const float4*)z_t,
                             (const float4*)w_prev, (const float4*)A_U,
                             CZ, Wh, AUh);
    // pre-pass 2: three weight transposes
    transpose3<<<dim3(64, 96, 3), dim3(32, 8)>>>(W_B, W_mod, A_V, WBT, WmT, AVT);

    // merged G2 (z=0, longest K first) + G1 (z=1) + G3 (z=2)
    GCfg3 cf;
    cf.g0 = { CZ, WBT, b_B,   Y2, 3072, 2048, 3072, 4, 16 };  // G2 -> fp16
    cf.g1 = { CZ, WmT, b_mod, Y1, 1024, 2048, 3072, 3, 16 };  // G1 tanh -> fp16
    cf.g2 = { Wh, AVT, nullptr, T, 2048, 512, 2048, 1, 4 };   // G3 -> fp16
    gemm_multi<<<dim3(16, 32, 3), 128, SMEM_TOTAL>>>(cf);

    // G4 fused finale (proven geometry)
    gemm_g4<<<dim3(16, 32), 128, SMEM_TOTAL>>>(T, AUh, Y1, Y2, Wh, A_diag, out);
}